// round 3
// baseline (speedup 1.0000x reference)
#include <cuda_runtime.h>

#define D 128
#define D4 32
#define MAXN 50176
#define MAXE 800000
#define ROWS3 64
#define THR3 512

typedef unsigned long long ull;

// ---- scratch (module-static device memory, zero-initialized at load) ----
__device__ __align__(16) float g_h[MAXN * D];   // gathered node features
__device__ __align__(16) float g_z[MAXN * D];   // normalized aggregate
__device__ int  g_cnt[MAXN];                    // in-degree (zeroed by k_out)
__device__ int  g_off[MAXN];                    // CSR offsets (end after perm)
__device__ __align__(8) int2 g_edge[MAXE];      // (src, etype) sorted by dst

#define FMA2(acc, a, b) \
    asm("fma.rn.f32x2 %0, %1, %2, %3;" : "=l"(acc) : "l"(a), "l"(b), "l"(acc))

// ---------------------------------------------------------------------------
// K1: grid-split: blocks [0, gb) gather h = prev[node_id];
//                 blocks [gb, ..) histogram dst into g_cnt.
// g_cnt is zero on entry (initial load zero-init; thereafter re-zeroed by k_out).
// ---------------------------------------------------------------------------
__global__ void k_prep(const float* __restrict__ prev,
                       const int* __restrict__ node_id,
                       const int* __restrict__ dst,
                       int n, int ne, int gb)
{
    if (blockIdx.x < gb) {
        int i = blockIdx.x * 256 + threadIdx.x;       // over n * D4 float4s
        if (i >= n * D4) return;
        int row = i >> 5, col = i & 31;
        int ent = __ldg(node_id + row);
        float4 v = __ldg(reinterpret_cast<const float4*>(prev) + (size_t)ent * D4 + col);
        reinterpret_cast<float4*>(g_h)[i] = v;
    } else {
        int e = (blockIdx.x - gb) * 256 + threadIdx.x;
        if (e >= ne) return;
        atomicAdd(&g_cnt[__ldg(dst + e)], 1);
    }
}

// ---------------------------------------------------------------------------
// K2: single-block exclusive scan of g_cnt -> g_off.
// All counts staged in dynamic smem; per-thread sequential + 2-level shfl scan.
// ---------------------------------------------------------------------------
__global__ void __launch_bounds__(1024, 1) k_scan(int n)
{
    extern __shared__ int sc[];
    __shared__ int wsum[32];
    int tid = threadIdx.x;

    for (int i = tid; i < n; i += 1024) sc[i] = g_cnt[i];
    __syncthreads();

    int items = (n + 1023) >> 10;
    int base = tid * items;
    int end = base + items; if (end > n) end = n;
    int sum = 0;
    for (int i = base; i < end; i++) sum += sc[i];

    int lane = tid & 31, wid = tid >> 5;
    int v = sum;
    #pragma unroll
    for (int o = 1; o < 32; o <<= 1) {
        int x = __shfl_up_sync(~0u, v, o);
        if (lane >= o) v += x;
    }
    if (lane == 31) wsum[wid] = v;
    __syncthreads();
    if (wid == 0) {
        int w = wsum[lane];
        #pragma unroll
        for (int o = 1; o < 32; o <<= 1) {
            int x = __shfl_up_sync(~0u, w, o);
            if (lane >= o) w += x;
        }
        wsum[lane] = w;                 // inclusive warp totals
    }
    __syncthreads();

    int run = v - sum + (wid > 0 ? wsum[wid - 1] : 0);   // exclusive prefix
    for (int i = base; i < end; i++) { g_off[i] = run; run += sc[i]; }
}

// ---------------------------------------------------------------------------
// K3: counting-sort edges by dst. Bumps g_off (becomes segment END).
// ---------------------------------------------------------------------------
__global__ void k_perm(const int* __restrict__ src, const int* __restrict__ dst,
                       const int* __restrict__ ety, int ne)
{
    int e = blockIdx.x * 256 + threadIdx.x;
    if (e >= ne) return;
    int d = __ldg(dst + e);
    int pos = atomicAdd(&g_off[d], 1);
    g_edge[pos] = make_int2(__ldg(src + e), __ldg(ety + e));
}

// ---------------------------------------------------------------------------
// K4: one warp per node: z = (1/cnt) * sum_e (h[src_e] + rel[etype_e])
// h rows via __ldcg (L2-only, streamed once) so L1 keeps the 256KB rel table.
// ---------------------------------------------------------------------------
__global__ void k_agg(const float* __restrict__ rel, int n)
{
    int lane = threadIdx.x & 31;
    int node = (blockIdx.x * blockDim.x + threadIdx.x) >> 5;
    if (node >= n) return;
    int cnt = __ldg(&g_cnt[node]);
    int beg = __ldg(&g_off[node]) - cnt;   // off was bumped to end by k_perm

    const float4* h4 = reinterpret_cast<const float4*>(g_h);
    const float4* r4 = reinterpret_cast<const float4*>(rel);

    float4 acc = make_float4(0.f, 0.f, 0.f, 0.f);
    int j = 0;
    for (; j + 3 < cnt; j += 4) {
        int2 e0 = __ldg(&g_edge[beg + j]);
        int2 e1 = __ldg(&g_edge[beg + j + 1]);
        int2 e2 = __ldg(&g_edge[beg + j + 2]);
        int2 e3 = __ldg(&g_edge[beg + j + 3]);
        float4 a0 = __ldcg(h4 + e0.x * D4 + lane);
        float4 a1 = __ldcg(h4 + e1.x * D4 + lane);
        float4 a2 = __ldcg(h4 + e2.x * D4 + lane);
        float4 a3 = __ldcg(h4 + e3.x * D4 + lane);
        float4 b0 = __ldg(r4 + e0.y * D4 + lane);
        float4 b1 = __ldg(r4 + e1.y * D4 + lane);
        float4 b2 = __ldg(r4 + e2.y * D4 + lane);
        float4 b3 = __ldg(r4 + e3.y * D4 + lane);
        acc.x += ((a0.x + b0.x) + (a1.x + b1.x)) + ((a2.x + b2.x) + (a3.x + b3.x));
        acc.y += ((a0.y + b0.y) + (a1.y + b1.y)) + ((a2.y + b2.y) + (a3.y + b3.y));
        acc.z += ((a0.z + b0.z) + (a1.z + b1.z)) + ((a2.z + b2.z) + (a3.z + b3.z));
        acc.w += ((a0.w + b0.w) + (a1.w + b1.w)) + ((a2.w + b2.w) + (a3.w + b3.w));
    }
    for (; j < cnt; j++) {
        int2 e0 = __ldg(&g_edge[beg + j]);
        float4 a0 = __ldcg(h4 + e0.x * D4 + lane);
        float4 b0 = __ldg(r4 + e0.y * D4 + lane);
        acc.x += a0.x + b0.x;
        acc.y += a0.y + b0.y;
        acc.z += a0.z + b0.z;
        acc.w += a0.w + b0.w;
    }
    float inv = (cnt > 0) ? 1.0f / (float)cnt : 0.f;
    acc.x *= inv; acc.y *= inv; acc.z *= inv; acc.w *= inv;
    reinterpret_cast<float4*>(g_z)[node * D4 + lane] = acc;
}

// ---------------------------------------------------------------------------
// K5: out = relu( z @ Wn + h @ (cnt>0 ? Wl : We) )
// Persistent; weights staged once per SM (k-pair layout); f32x2 FMA mainloop.
// Also re-zeros g_cnt for the next graph replay.
// ---------------------------------------------------------------------------
__global__ void __launch_bounds__(THR3, 1)
k_out(const float* __restrict__ Wl, const float* __restrict__ We,
      const float* __restrict__ Wn, float* __restrict__ out, int n)
{
    extern __shared__ float sm[];
    float* WnP  = sm;                     // 64*256
    float* WlP  = WnP + 64 * 256;         // 64*256
    float* zs   = WlP + 64 * 256;         // ROWS3*D
    float* hs   = zs + ROWS3 * D;         // ROWS3*D
    float* degs = hs + ROWS3 * D;         // ROWS3

    int tid = threadIdx.x;

    // stage weights once (k-pair layout): WP[kp*256 + c*2 + (k&1)] = W[k*D + c]
    for (int i = tid; i < D * D; i += THR3) {
        int k = i >> 7, c = i & 127;
        float wn = __ldg(Wn + i);
        float wl = __ldg(Wl + i);
        int idx = (k >> 1) * 256 + c * 2 + (k & 1);
        WnP[idx] = wn;
        WlP[idx] = wl;
    }

    int cg = (tid & 63) * 2;
    int rg = (tid >> 6) * 8;
    int ntile = (n + ROWS3 - 1) / ROWS3;

    for (int tile = blockIdx.x; tile < ntile; tile += gridDim.x) {
        int row0 = tile * ROWS3;
        __syncthreads();
        for (int i = tid; i < ROWS3 * D4; i += THR3) {
            int r = i >> 5, c = i & 31;
            int gr = row0 + r;
            float4 zv = make_float4(0.f, 0.f, 0.f, 0.f);
            float4 hv = zv;
            if (gr < n) {
                zv = reinterpret_cast<const float4*>(g_z)[gr * D4 + c];
                hv = reinterpret_cast<const float4*>(g_h)[gr * D4 + c];
                if (c == 0) {
                    degs[r] = (float)g_cnt[gr];
                    g_cnt[gr] = 0;        // reset for next replay
                }
            } else if (c == 0) {
                degs[r] = 1.f;
            }
            reinterpret_cast<float4*>(zs)[i] = zv;
            reinterpret_cast<float4*>(hs)[i] = hv;
        }
        __syncthreads();

        ull accN[8][2] = {};
        ull accL[8][2] = {};

        #pragma unroll 4
        for (int k4 = 0; k4 < D; k4 += 4) {
            int kp = k4 >> 1;
            const float* wq = WnP + kp * 256 + cg * 2;
            const float* wr = WlP + kp * 256 + cg * 2;
            longlong2 wnA = *reinterpret_cast<const longlong2*>(wq);
            longlong2 wnB = *reinterpret_cast<const longlong2*>(wq + 256);
            longlong2 wlA = *reinterpret_cast<const longlong2*>(wr);
            longlong2 wlB = *reinterpret_cast<const longlong2*>(wr + 256);
            #pragma unroll
            for (int r = 0; r < 8; r++) {
                longlong2 zz = *reinterpret_cast<const longlong2*>(zs + (rg + r) * D + k4);
                longlong2 hh = *reinterpret_cast<const longlong2*>(hs + (rg + r) * D + k4);
                ull zx = (ull)zz.x, zy = (ull)zz.y;
                ull hx = (ull)hh.x, hy = (ull)hh.y;
                FMA2(accN[r][0], zx, (ull)wnA.x);
                FMA2(accN[r][1], zx, (ull)wnA.y);
                FMA2(accN[r][0], zy, (ull)wnB.x);
                FMA2(accN[r][1], zy, (ull)wnB.y);
                FMA2(accL[r][0], hx, (ull)wlA.x);
                FMA2(accL[r][1], hx, (ull)wlA.y);
                FMA2(accL[r][0], hy, (ull)wlB.x);
                FMA2(accL[r][1], hy, (ull)wlB.y);
            }
        }

        #pragma unroll
        for (int r = 0; r < 8; r++) {
            int gr = row0 + rg + r;
            if (gr >= n) continue;
            float n0 = __uint_as_float((unsigned)accN[r][0]) +
                       __uint_as_float((unsigned)(accN[r][0] >> 32));
            float n1 = __uint_as_float((unsigned)accN[r][1]) +
                       __uint_as_float((unsigned)(accN[r][1] >> 32));
            float l0 = __uint_as_float((unsigned)accL[r][0]) +
                       __uint_as_float((unsigned)(accL[r][0] >> 32));
            float l1 = __uint_as_float((unsigned)accL[r][1]) +
                       __uint_as_float((unsigned)(accL[r][1] >> 32));
            if (degs[rg + r] <= 0.f) {
                // rare: no in-edges -> self-loop uses evolve_loop_weight
                l0 = 0.f; l1 = 0.f;
                for (int k = 0; k < D; k++) {
                    float hk = hs[(rg + r) * D + k];
                    l0 += hk * __ldg(We + k * D + cg);
                    l1 += hk * __ldg(We + k * D + cg + 1);
                }
            }
            float v0 = n0 + l0;
            float v1 = n1 + l1;
            float2 o = make_float2(v0 > 0.f ? v0 : 0.f, v1 > 0.f ? v1 : 0.f);
            *reinterpret_cast<float2*>(out + (size_t)gr * D + cg) = o;
        }
    }
}

// ---------------------------------------------------------------------------
extern "C" void kernel_launch(void* const* d_in, const int* in_sizes, int n_in,
                              void* d_out, int out_size)
{
    const float* prev    = (const float*)d_in[0];
    const float* rel     = (const float*)d_in[1];
    const float* Wl      = (const float*)d_in[2];
    const float* We      = (const float*)d_in[3];
    const float* Wn      = (const float*)d_in[4];
    const int*   node_id = (const int*)d_in[5];
    const int*   src     = (const int*)d_in[6];
    const int*   dst     = (const int*)d_in[7];
    const int*   ety     = (const int*)d_in[8];
    float* out = (float*)d_out;

    int n_nodes = in_sizes[5];
    int n_edges = in_sizes[6];

    // K1: gather + histogram (grid-split)
    int gb = (n_nodes * D4 + 255) / 256;
    int hb = (n_edges + 255) / 256;
    k_prep<<<gb + hb, 256>>>(prev, node_id, dst, n_nodes, n_edges, gb);

    // K2: single-block scan
    {
        size_t smem = (size_t)n_nodes * sizeof(int);
        cudaFuncSetAttribute(k_scan, cudaFuncAttributeMaxDynamicSharedMemorySize,
                             (int)smem);
        k_scan<<<1, 1024, smem>>>(n_nodes);
    }

    // K3: counting-sort edges by dst
    k_perm<<<(n_edges + 255) / 256, 256>>>(src, dst, ety, n_edges);

    // K4: per-node aggregation (normalized)
    k_agg<<<(n_nodes * 32 + 255) / 256, 256>>>(rel, n_nodes);

    // K5: fused output GEMM (persistent, f32x2) + g_cnt reset
    {
        size_t smem = (size_t)(2 * 64 * 256 + 2 * ROWS3 * D + ROWS3) * sizeof(float);
        cudaFuncSetAttribute(k_out, cudaFuncAttributeMaxDynamicSharedMemorySize,
                             (int)smem);
        k_out<<<148, THR3, smem>>>(Wl, We, Wn, out, n_nodes);
    }
}

// round 4
// speedup vs baseline: 1.1059x; 1.1059x over previous
#include <cuda_runtime.h>

#define D 128
#define D4 32
#define MAXN 50176
#define MAXE 800000
#define ROWS3 64
#define THR3 128

typedef unsigned long long ull;

// ---- scratch (module-static device memory, zero-initialized at load) ----
__device__ __align__(16) float g_h[MAXN * D];   // gathered node features
__device__ __align__(16) float g_z[MAXN * D];   // normalized aggregate
__device__ int  g_cnt[MAXN];                    // in-degree (zeroed by k_out)
__device__ int  g_off[MAXN];                    // CSR offsets (end after perm)
__device__ int  g_bsum[128];                    // scan chunk sums
__device__ __align__(8) int2 g_edge[MAXE];      // (src, etype) sorted by dst

#define FMA2(acc, a, b) \
    asm("fma.rn.f32x2 %0, %1, %2, %3;" : "=l"(acc) : "l"(a), "l"(b), "l"(acc))

// ---------------------------------------------------------------------------
// K1: grid-split: blocks [0, gb) gather h = prev[node_id];
//                 blocks [gb, ..) histogram dst into g_cnt.
// g_cnt is zero on entry (load-time zero-init; thereafter re-zeroed by k_out).
// ---------------------------------------------------------------------------
__global__ void k_prep(const float* __restrict__ prev,
                       const int* __restrict__ node_id,
                       const int* __restrict__ dst,
                       int n, int ne, int gb)
{
    if (blockIdx.x < gb) {
        int i = blockIdx.x * 256 + threadIdx.x;
        if (i >= n * D4) return;
        int row = i >> 5, col = i & 31;
        int ent = __ldg(node_id + row);
        float4 v = __ldg(reinterpret_cast<const float4*>(prev) + (size_t)ent * D4 + col);
        reinterpret_cast<float4*>(g_h)[i] = v;
    } else {
        int e = (blockIdx.x - gb) * 256 + threadIdx.x;
        if (e >= ne) return;
        atomicAdd(&g_cnt[__ldg(dst + e)], 1);
    }
}

// ---------------------------------------------------------------------------
// K2a/b/c: chunked exclusive scan of g_cnt -> g_off (R2-proven, small smem)
// ---------------------------------------------------------------------------
__global__ void k_scan1(int n)
{
    __shared__ int sm[1024];
    int t = threadIdx.x;
    int i = blockIdx.x * 1024 + t;
    int v = (i < n) ? g_cnt[i] : 0;
    sm[t] = v;
    __syncthreads();
    #pragma unroll
    for (int off = 1; off < 1024; off <<= 1) {
        int x = (t >= off) ? sm[t - off] : 0;
        __syncthreads();
        sm[t] += x;
        __syncthreads();
    }
    if (i < n) g_off[i] = sm[t] - v;
    if (t == 1023) g_bsum[blockIdx.x] = sm[t];
}

__global__ void k_scan2(int nchunks)
{
    __shared__ int sm[128];
    int t = threadIdx.x;
    if (t < nchunks) sm[t] = g_bsum[t];
    __syncthreads();
    if (t == 0) {
        int run = 0;
        for (int b = 0; b < nchunks; b++) { int x = sm[b]; sm[b] = run; run += x; }
    }
    __syncthreads();
    if (t < nchunks) g_bsum[t] = sm[t];
}

__global__ void k_scan3(int n)
{
    int i = blockIdx.x * 256 + threadIdx.x;
    if (i >= n) return;
    g_off[i] += g_bsum[i >> 10];
}

// ---------------------------------------------------------------------------
// K3: counting-sort edges by dst. Bumps g_off (becomes segment END).
// ---------------------------------------------------------------------------
__global__ void k_perm(const int* __restrict__ src, const int* __restrict__ dst,
                       const int* __restrict__ ety, int ne)
{
    int e = blockIdx.x * 256 + threadIdx.x;
    if (e >= ne) return;
    int d = __ldg(dst + e);
    int pos = atomicAdd(&g_off[d], 1);
    g_edge[pos] = make_int2(__ldg(src + e), __ldg(ety + e));
}

// ---------------------------------------------------------------------------
// K4: one warp per node: z = (1/cnt) * sum_e (h[src_e] + rel[etype_e])
// ---------------------------------------------------------------------------
__global__ void k_agg(const float* __restrict__ rel, int n)
{
    int lane = threadIdx.x & 31;
    int node = (blockIdx.x * blockDim.x + threadIdx.x) >> 5;
    if (node >= n) return;
    int cnt = __ldg(&g_cnt[node]);
    int beg = __ldg(&g_off[node]) - cnt;

    const float4* h4 = reinterpret_cast<const float4*>(g_h);
    const float4* r4 = reinterpret_cast<const float4*>(rel);

    float4 acc = make_float4(0.f, 0.f, 0.f, 0.f);
    int j = 0;
    for (; j + 3 < cnt; j += 4) {
        int2 e0 = __ldg(&g_edge[beg + j]);
        int2 e1 = __ldg(&g_edge[beg + j + 1]);
        int2 e2 = __ldg(&g_edge[beg + j + 2]);
        int2 e3 = __ldg(&g_edge[beg + j + 3]);
        float4 a0 = __ldcg(h4 + e0.x * D4 + lane);
        float4 a1 = __ldcg(h4 + e1.x * D4 + lane);
        float4 a2 = __ldcg(h4 + e2.x * D4 + lane);
        float4 a3 = __ldcg(h4 + e3.x * D4 + lane);
        float4 b0 = __ldg(r4 + e0.y * D4 + lane);
        float4 b1 = __ldg(r4 + e1.y * D4 + lane);
        float4 b2 = __ldg(r4 + e2.y * D4 + lane);
        float4 b3 = __ldg(r4 + e3.y * D4 + lane);
        acc.x += ((a0.x + b0.x) + (a1.x + b1.x)) + ((a2.x + b2.x) + (a3.x + b3.x));
        acc.y += ((a0.y + b0.y) + (a1.y + b1.y)) + ((a2.y + b2.y) + (a3.y + b3.y));
        acc.z += ((a0.z + b0.z) + (a1.z + b1.z)) + ((a2.z + b2.z) + (a3.z + b3.z));
        acc.w += ((a0.w + b0.w) + (a1.w + b1.w)) + ((a2.w + b2.w) + (a3.w + b3.w));
    }
    for (; j < cnt; j++) {
        int2 e0 = __ldg(&g_edge[beg + j]);
        float4 a0 = __ldcg(h4 + e0.x * D4 + lane);
        float4 b0 = __ldg(r4 + e0.y * D4 + lane);
        acc.x += a0.x + b0.x;
        acc.y += a0.y + b0.y;
        acc.z += a0.z + b0.z;
        acc.w += a0.w + b0.w;
    }
    float inv = (cnt > 0) ? 1.0f / (float)cnt : 0.f;
    acc.x *= inv; acc.y *= inv; acc.z *= inv; acc.w *= inv;
    reinterpret_cast<float4*>(g_z)[node * D4 + lane] = acc;
}

// ---------------------------------------------------------------------------
// K5: out = relu( [z|h] @ [Wn;Wl] ) as ONE K=256 GEMM.
// 128 threads, 64-row tiles, 8x8 register tile per thread, f32x2 over k-pairs.
// Combined weights staged once per SM in k-pair layout:
//   WCP[kp*256 + c*2 + (k&1)] = WC[k][c],  WC = vstack(Wn, Wl), K=256.
// Rare deg==0 rows corrected with += h @ (We - Wl). Re-zeros g_cnt.
// ---------------------------------------------------------------------------
__global__ void __launch_bounds__(THR3, 1)
k_out(const float* __restrict__ Wl, const float* __restrict__ We,
      const float* __restrict__ Wn, float* __restrict__ out, int n)
{
    extern __shared__ float sm[];
    float* WCP  = sm;                     // 128*256 floats (128KB)
    float* as   = WCP + 128 * 256;        // ROWS3*256 floats (64KB)
    float* degs = as + ROWS3 * 256;       // ROWS3

    int tid = threadIdx.x;

    // stage combined weights once, k-pair layout
    for (int i = tid; i < 2 * D * D; i += THR3) {
        int k = i >> 7, c = i & 127;
        float w = (k < D) ? __ldg(Wn + k * D + c) : __ldg(Wl + (k - D) * D + c);
        WCP[(k >> 1) * 256 + c * 2 + (k & 1)] = w;
    }

    int cg = (tid & 15) * 8;              // 8 output columns
    int rg = (tid >> 4) * 8;              // 8 rows
    int ntile = (n + ROWS3 - 1) / ROWS3;

    for (int tile = blockIdx.x; tile < ntile; tile += gridDim.x) {
        int row0 = tile * ROWS3;
        __syncthreads();
        // stage combined activations: as[r][0:128]=z[row], as[r][128:256]=h[row]
        #pragma unroll 4
        for (int i = tid; i < ROWS3 * 64; i += THR3) {
            int r = i >> 6, q = i & 63;
            int gr = row0 + r;
            float4 v = make_float4(0.f, 0.f, 0.f, 0.f);
            if (gr < n) {
                v = (q < 32) ? __ldcg(reinterpret_cast<const float4*>(g_z) + gr * D4 + q)
                             : __ldcg(reinterpret_cast<const float4*>(g_h) + gr * D4 + q - 32);
            }
            reinterpret_cast<float4*>(as)[i] = v;
        }
        if (tid < ROWS3) {
            int gr = row0 + tid;
            if (gr < n) { degs[tid] = (float)g_cnt[gr]; g_cnt[gr] = 0; }
            else degs[tid] = 1.f;
        }
        __syncthreads();

        ull acc[8][8] = {};

        #pragma unroll 4
        for (int kp = 0; kp < 128; kp += 2) {     // 2 k-pairs = 4 k's per iter
            const float* wq = WCP + kp * 256 + cg * 2;
            longlong2 wA[4], wB[4];
            #pragma unroll
            for (int c = 0; c < 4; c++) {
                wA[c] = *reinterpret_cast<const longlong2*>(wq + c * 4);
                wB[c] = *reinterpret_cast<const longlong2*>(wq + 256 + c * 4);
            }
            #pragma unroll
            for (int r = 0; r < 8; r++) {
                longlong2 aa = *reinterpret_cast<const longlong2*>(as + (rg + r) * 256 + kp * 2);
                ull a0 = (ull)aa.x, a1 = (ull)aa.y;
                #pragma unroll
                for (int c = 0; c < 4; c++) {
                    FMA2(acc[r][2 * c],     a0, (ull)wA[c].x);
                    FMA2(acc[r][2 * c + 1], a0, (ull)wA[c].y);
                    FMA2(acc[r][2 * c],     a1, (ull)wB[c].x);
                    FMA2(acc[r][2 * c + 1], a1, (ull)wB[c].y);
                }
            }
        }

        #pragma unroll
        for (int r = 0; r < 8; r++) {
            int gr = row0 + rg + r;
            if (gr >= n) continue;
            float v[8];
            #pragma unroll
            for (int c = 0; c < 8; c++)
                v[c] = __uint_as_float((unsigned)acc[r][c]) +
                       __uint_as_float((unsigned)(acc[r][c] >> 32));
            if (degs[rg + r] <= 0.f) {
                // rare: no in-edges -> self-loop uses We instead of Wl
                for (int k = 0; k < D; k++) {
                    float hk = as[(rg + r) * 256 + D + k];
                    #pragma unroll
                    for (int c = 0; c < 8; c++)
                        v[c] += hk * (__ldg(We + k * D + cg + c) - __ldg(Wl + k * D + cg + c));
                }
            }
            float4 o0 = make_float4(v[0] > 0.f ? v[0] : 0.f, v[1] > 0.f ? v[1] : 0.f,
                                    v[2] > 0.f ? v[2] : 0.f, v[3] > 0.f ? v[3] : 0.f);
            float4 o1 = make_float4(v[4] > 0.f ? v[4] : 0.f, v[5] > 0.f ? v[5] : 0.f,
                                    v[6] > 0.f ? v[6] : 0.f, v[7] > 0.f ? v[7] : 0.f);
            *reinterpret_cast<float4*>(out + (size_t)gr * D + cg) = o0;
            *reinterpret_cast<float4*>(out + (size_t)gr * D + cg + 4) = o1;
        }
    }
}

// ---------------------------------------------------------------------------
extern "C" void kernel_launch(void* const* d_in, const int* in_sizes, int n_in,
                              void* d_out, int out_size)
{
    const float* prev    = (const float*)d_in[0];
    const float* rel     = (const float*)d_in[1];
    const float* Wl      = (const float*)d_in[2];
    const float* We      = (const float*)d_in[3];
    const float* Wn      = (const float*)d_in[4];
    const int*   node_id = (const int*)d_in[5];
    const int*   src     = (const int*)d_in[6];
    const int*   dst     = (const int*)d_in[7];
    const int*   ety     = (const int*)d_in[8];
    float* out = (float*)d_out;

    int n_nodes = in_sizes[5];
    int n_edges = in_sizes[6];
    int nchunks = (n_nodes + 1023) / 1024;

    // K1: gather + histogram (grid-split)
    int gb = (n_nodes * D4 + 255) / 256;
    int hb = (n_edges + 255) / 256;
    k_prep<<<gb + hb, 256>>>(prev, node_id, dst, n_nodes, n_edges, gb);

    // K2: chunked scan (small smem, proven in R2)
    k_scan1<<<nchunks, 1024>>>(n_nodes);
    k_scan2<<<1, 128>>>(nchunks);
    k_scan3<<<(n_nodes + 255) / 256, 256>>>(n_nodes);

    // K3: counting-sort edges by dst
    k_perm<<<(n_edges + 255) / 256, 256>>>(src, dst, ety, n_edges);

    // K4: per-node aggregation (normalized)
    k_agg<<<(n_nodes * 32 + 255) / 256, 256>>>(rel, n_nodes);

    // K5: fused single-GEMM output (persistent, f32x2) + g_cnt reset
    {
        size_t smem = (size_t)(128 * 256 + ROWS3 * 256 + ROWS3) * sizeof(float);
        cudaFuncSetAttribute(k_out, cudaFuncAttributeMaxDynamicSharedMemorySize,
                             (int)smem);
        k_out<<<148, THR3, smem>>>(Wl, We, Wn, out, n_nodes);
    }
}

// round 5
// speedup vs baseline: 1.8456x; 1.6690x over previous
#include <cuda_runtime.h>

#define D 128
#define D4 32
#define MAXN 50176
#define MAXE 800000
#define ROWS3 64
#define THR3 512

typedef unsigned long long ull;

// ---- scratch (module-static device memory, zero-initialized at load) ----
__device__ __align__(16) float g_h[MAXN * D];   // gathered node features
__device__ __align__(16) float g_z[MAXN * D];   // normalized aggregate
__device__ int   g_cnt[MAXN];                   // in-degree (zeroed by k_out)
__device__ int   g_off[MAXN];                   // CSR offsets (end after perm)
__device__ float g_deg[MAXN];                   // in-degree as float
__device__ int   g_bsum[128];                   // scan chunk sums
__device__ __align__(8) int2 g_edge[MAXE];      // (src, etype) sorted by dst

#define FMA2(acc, a, b) \
    asm("fma.rn.f32x2 %0, %1, %2, %3;" : "=l"(acc) : "l"(a), "l"(b), "l"(acc))

// ---------------------------------------------------------------------------
// K1: grid-split: blocks [0, gb) gather h = prev[node_id];
//                 blocks [gb, ..) histogram dst into g_cnt.
// g_cnt is zero on entry (load-time zero-init; re-zeroed by k_out each run).
// ---------------------------------------------------------------------------
__global__ void k_prep(const float* __restrict__ prev,
                       const int* __restrict__ node_id,
                       const int* __restrict__ dst,
                       int n, int ne, int gb)
{
    if (blockIdx.x < gb) {
        int i = blockIdx.x * 256 + threadIdx.x;
        if (i >= n * D4) return;
        int row = i >> 5, col = i & 31;
        int ent = __ldg(node_id + row);
        float4 v = __ldg(reinterpret_cast<const float4*>(prev) + (size_t)ent * D4 + col);
        reinterpret_cast<float4*>(g_h)[i] = v;
    } else {
        int e = (blockIdx.x - gb) * 256 + threadIdx.x;
        if (e >= ne) return;
        atomicAdd(&g_cnt[__ldg(dst + e)], 1);
    }
}

// ---------------------------------------------------------------------------
// K2a: per-chunk exclusive scan of g_cnt -> g_off; chunk totals -> g_bsum
// ---------------------------------------------------------------------------
__global__ void k_scan1(int n)
{
    __shared__ int sm[1024];
    int t = threadIdx.x;
    int i = blockIdx.x * 1024 + t;
    int v = (i < n) ? g_cnt[i] : 0;
    sm[t] = v;
    __syncthreads();
    #pragma unroll
    for (int off = 1; off < 1024; off <<= 1) {
        int x = (t >= off) ? sm[t - off] : 0;
        __syncthreads();
        sm[t] += x;
        __syncthreads();
    }
    if (i < n) g_off[i] = sm[t] - v;
    if (t == 1023) g_bsum[blockIdx.x] = sm[t];
}

// ---------------------------------------------------------------------------
// K2b: add chunk-prefix (computed inline from <=128 chunk sums); write g_deg
// ---------------------------------------------------------------------------
__global__ void k_scan3(int n, int nchunks)
{
    __shared__ int sb[128];
    int t = threadIdx.x;
    if (t < nchunks) sb[t] = g_bsum[t];
    __syncthreads();
    int i = blockIdx.x * 256 + t;
    if (i >= n) return;
    int chunk = i >> 10;
    int pre = 0;
    for (int j = 0; j < chunk; j++) pre += sb[j];
    g_off[i] += pre;
    g_deg[i] = (float)g_cnt[i];
}

// ---------------------------------------------------------------------------
// K3: counting-sort edges by dst. Bumps g_off (becomes segment END).
// ---------------------------------------------------------------------------
__global__ void k_perm(const int* __restrict__ src, const int* __restrict__ dst,
                       const int* __restrict__ ety, int ne)
{
    int e = blockIdx.x * 256 + threadIdx.x;
    if (e >= ne) return;
    int d = __ldg(dst + e);
    int pos = atomicAdd(&g_off[d], 1);
    g_edge[pos] = make_int2(__ldg(src + e), __ldg(ety + e));
}

// ---------------------------------------------------------------------------
// K4: one warp per node: z = (1/cnt) * sum_e (h[src_e] + rel[etype_e])
// h rows via __ldcg (streamed once) so L1 keeps the 256KB rel table.
// ---------------------------------------------------------------------------
__global__ void k_agg(const float* __restrict__ rel, int n)
{
    int lane = threadIdx.x & 31;
    int node = (blockIdx.x * blockDim.x + threadIdx.x) >> 5;
    if (node >= n) return;
    int cnt = __ldg(&g_cnt[node]);
    int beg = __ldg(&g_off[node]) - cnt;

    const float4* h4 = reinterpret_cast<const float4*>(g_h);
    const float4* r4 = reinterpret_cast<const float4*>(rel);

    float4 acc = make_float4(0.f, 0.f, 0.f, 0.f);
    int j = 0;
    for (; j + 3 < cnt; j += 4) {
        int2 e0 = __ldg(&g_edge[beg + j]);
        int2 e1 = __ldg(&g_edge[beg + j + 1]);
        int2 e2 = __ldg(&g_edge[beg + j + 2]);
        int2 e3 = __ldg(&g_edge[beg + j + 3]);
        float4 a0 = __ldcg(h4 + e0.x * D4 + lane);
        float4 a1 = __ldcg(h4 + e1.x * D4 + lane);
        float4 a2 = __ldcg(h4 + e2.x * D4 + lane);
        float4 a3 = __ldcg(h4 + e3.x * D4 + lane);
        float4 b0 = __ldg(r4 + e0.y * D4 + lane);
        float4 b1 = __ldg(r4 + e1.y * D4 + lane);
        float4 b2 = __ldg(r4 + e2.y * D4 + lane);
        float4 b3 = __ldg(r4 + e3.y * D4 + lane);
        acc.x += ((a0.x + b0.x) + (a1.x + b1.x)) + ((a2.x + b2.x) + (a3.x + b3.x));
        acc.y += ((a0.y + b0.y) + (a1.y + b1.y)) + ((a2.y + b2.y) + (a3.y + b3.y));
        acc.z += ((a0.z + b0.z) + (a1.z + b1.z)) + ((a2.z + b2.z) + (a3.z + b3.z));
        acc.w += ((a0.w + b0.w) + (a1.w + b1.w)) + ((a2.w + b2.w) + (a3.w + b3.w));
    }
    for (; j < cnt; j++) {
        int2 e0 = __ldg(&g_edge[beg + j]);
        float4 a0 = __ldcg(h4 + e0.x * D4 + lane);
        float4 b0 = __ldg(r4 + e0.y * D4 + lane);
        acc.x += a0.x + b0.x;
        acc.y += a0.y + b0.y;
        acc.z += a0.z + b0.z;
        acc.w += a0.w + b0.w;
    }
    float inv = (cnt > 0) ? 1.0f / (float)cnt : 0.f;
    acc.x *= inv; acc.y *= inv; acc.z *= inv; acc.w *= inv;
    reinterpret_cast<float4*>(g_z)[node * D4 + lane] = acc;
}

// ---------------------------------------------------------------------------
// K5: out = relu( z @ Wn + h @ (deg>0 ? Wl : We) )   [R2-proven structure]
// Persistent; weights staged once per SM (k-pair layout); f32x2 FMA mainloop.
// 512 threads, 64-row tiles, per-thread 8 rows x 2 cols per GEMM.
// Also re-zeros g_cnt for the next graph replay.
// ---------------------------------------------------------------------------
__global__ void __launch_bounds__(THR3, 1)
k_out(const float* __restrict__ Wl, const float* __restrict__ We,
      const float* __restrict__ Wn, float* __restrict__ out, int n)
{
    extern __shared__ float sm[];
    float* WnP  = sm;                     // 64*256
    float* WlP  = WnP + 64 * 256;         // 64*256
    float* zs   = WlP + 64 * 256;         // ROWS3*D
    float* hs   = zs + ROWS3 * D;         // ROWS3*D
    float* degs = hs + ROWS3 * D;         // ROWS3

    int tid = threadIdx.x;

    // stage weights once (k-pair layout): WP[kp*256 + c*2 + (k&1)] = W[k*D + c]
    for (int i = tid; i < D * D; i += THR3) {
        int k = i >> 7, c = i & 127;
        float wn = __ldg(Wn + i);
        float wl = __ldg(Wl + i);
        int idx = (k >> 1) * 256 + c * 2 + (k & 1);
        WnP[idx] = wn;
        WlP[idx] = wl;
    }

    int cg = (tid & 63) * 2;
    int rg = (tid >> 6) * 8;
    int ntile = (n + ROWS3 - 1) / ROWS3;

    for (int tile = blockIdx.x; tile < ntile; tile += gridDim.x) {
        int row0 = tile * ROWS3;
        __syncthreads();
        for (int i = tid; i < ROWS3 * D4; i += THR3) {
            int r = i >> 5, c = i & 31;
            int gr = row0 + r;
            float4 zv = make_float4(0.f, 0.f, 0.f, 0.f);
            float4 hv = zv;
            if (gr < n) {
                zv = __ldcg(reinterpret_cast<const float4*>(g_z) + gr * D4 + c);
                hv = __ldcg(reinterpret_cast<const float4*>(g_h) + gr * D4 + c);
                if (c == 0) {
                    degs[r] = g_deg[gr];
                    g_cnt[gr] = 0;        // reset for next replay
                }
            } else if (c == 0) {
                degs[r] = 1.f;
            }
            reinterpret_cast<float4*>(zs)[i] = zv;
            reinterpret_cast<float4*>(hs)[i] = hv;
        }
        __syncthreads();

        ull accN[8][2] = {};
        ull accL[8][2] = {};

        #pragma unroll 4
        for (int k4 = 0; k4 < D; k4 += 4) {
            int kp = k4 >> 1;
            const float* wq = WnP + kp * 256 + cg * 2;
            const float* wr = WlP + kp * 256 + cg * 2;
            longlong2 wnA = *reinterpret_cast<const longlong2*>(wq);
            longlong2 wnB = *reinterpret_cast<const longlong2*>(wq + 256);
            longlong2 wlA = *reinterpret_cast<const longlong2*>(wr);
            longlong2 wlB = *reinterpret_cast<const longlong2*>(wr + 256);
            #pragma unroll
            for (int r = 0; r < 8; r++) {
                longlong2 zz = *reinterpret_cast<const longlong2*>(zs + (rg + r) * D + k4);
                longlong2 hh = *reinterpret_cast<const longlong2*>(hs + (rg + r) * D + k4);
                ull zx = (ull)zz.x, zy = (ull)zz.y;
                ull hx = (ull)hh.x, hy = (ull)hh.y;
                FMA2(accN[r][0], zx, (ull)wnA.x);
                FMA2(accN[r][1], zx, (ull)wnA.y);
                FMA2(accN[r][0], zy, (ull)wnB.x);
                FMA2(accN[r][1], zy, (ull)wnB.y);
                FMA2(accL[r][0], hx, (ull)wlA.x);
                FMA2(accL[r][1], hx, (ull)wlA.y);
                FMA2(accL[r][0], hy, (ull)wlB.x);
                FMA2(accL[r][1], hy, (ull)wlB.y);
            }
        }

        #pragma unroll
        for (int r = 0; r < 8; r++) {
            int gr = row0 + rg + r;
            if (gr >= n) continue;
            float n0 = __uint_as_float((unsigned)accN[r][0]) +
                       __uint_as_float((unsigned)(accN[r][0] >> 32));
            float n1 = __uint_as_float((unsigned)accN[r][1]) +
                       __uint_as_float((unsigned)(accN[r][1] >> 32));
            float l0 = __uint_as_float((unsigned)accL[r][0]) +
                       __uint_as_float((unsigned)(accL[r][0] >> 32));
            float l1 = __uint_as_float((unsigned)accL[r][1]) +
                       __uint_as_float((unsigned)(accL[r][1] >> 32));
            if (degs[rg + r] <= 0.f) {
                // rare: no in-edges -> self-loop uses evolve_loop_weight
                l0 = 0.f; l1 = 0.f;
                for (int k = 0; k < D; k++) {
                    float hk = hs[(rg + r) * D + k];
                    l0 += hk * __ldg(We + k * D + cg);
                    l1 += hk * __ldg(We + k * D + cg + 1);
                }
            }
            float v0 = n0 + l0;
            float v1 = n1 + l1;
            float2 o = make_float2(v0 > 0.f ? v0 : 0.f, v1 > 0.f ? v1 : 0.f);
            *reinterpret_cast<float2*>(out + (size_t)gr * D + cg) = o;
        }
    }
}

// ---------------------------------------------------------------------------
extern "C" void kernel_launch(void* const* d_in, const int* in_sizes, int n_in,
                              void* d_out, int out_size)
{
    const float* prev    = (const float*)d_in[0];
    const float* rel     = (const float*)d_in[1];
    const float* Wl      = (const float*)d_in[2];
    const float* We      = (const float*)d_in[3];
    const float* Wn      = (const float*)d_in[4];
    const int*   node_id = (const int*)d_in[5];
    const int*   src     = (const int*)d_in[6];
    const int*   dst     = (const int*)d_in[7];
    const int*   ety     = (const int*)d_in[8];
    float* out = (float*)d_out;

    int n_nodes = in_sizes[5];
    int n_edges = in_sizes[6];
    int nchunks = (n_nodes + 1023) / 1024;

    // K1: gather + histogram (grid-split)
    int gb = (n_nodes * D4 + 255) / 256;
    int hb = (n_edges + 255) / 256;
    k_prep<<<gb + hb, 256>>>(prev, node_id, dst, n_nodes, n_edges, gb);

    // K2: scan (2 kernels)
    k_scan1<<<nchunks, 1024>>>(n_nodes);
    k_scan3<<<(n_nodes + 255) / 256, 256>>>(n_nodes, nchunks);

    // K3: counting-sort edges by dst
    k_perm<<<(n_edges + 255) / 256, 256>>>(src, dst, ety, n_edges);

    // K4: per-node aggregation (normalized)
    k_agg<<<(n_nodes * 32 + 255) / 256, 256>>>(rel, n_nodes);

    // K5: fused output GEMM (persistent, f32x2, R2-proven) + g_cnt reset
    {
        size_t smem = (size_t)(2 * 64 * 256 + 2 * ROWS3 * D + ROWS3) * sizeof(float);
        cudaFuncSetAttribute(k_out, cudaFuncAttributeMaxDynamicSharedMemorySize,
                             (int)smem);
        k_out<<<148, THR3, smem>>>(Wl, We, Wn, out, n_nodes);
    }
}

// round 7
// speedup vs baseline: 2.2997x; 1.2460x over previous
#include <cuda_runtime.h>
#include <cuda_bf16.h>
#include <cstdint>

#define D 128
#define D4 32
#define MAXN 50176
#define MAXE 800000

typedef unsigned long long ull;

// ---- scratch (module-static device memory, zero-initialized at load) ----
__device__ __align__(16) float g_h[MAXN * D];   // gathered node features
__device__ __align__(16) float g_z[MAXN * D];   // normalized aggregate
__device__ int   g_cnt[MAXN];                   // in-degree (zeroed by k_out)
__device__ int   g_off[MAXN];                   // CSR offsets (end after perm)
__device__ int   g_bsum[128];                   // scan chunk sums
__device__ __align__(8) int2 g_edge[MAXE];      // (src, etype) sorted by dst

// ---------------------------------------------------------------------------
// K1: grid-split: gather h = prev[node_id]  |  histogram dst into g_cnt
// ---------------------------------------------------------------------------
__global__ void k_prep(const float* __restrict__ prev,
                       const int* __restrict__ node_id,
                       const int* __restrict__ dst,
                       int n, int ne, int gb)
{
    if (blockIdx.x < gb) {
        int i = blockIdx.x * 256 + threadIdx.x;
        if (i >= n * D4) return;
        int row = i >> 5, col = i & 31;
        int ent = __ldg(node_id + row);
        float4 v = __ldg(reinterpret_cast<const float4*>(prev) + (size_t)ent * D4 + col);
        reinterpret_cast<float4*>(g_h)[i] = v;
    } else {
        int e = (blockIdx.x - gb) * 256 + threadIdx.x;
        if (e >= ne) return;
        atomicAdd(&g_cnt[__ldg(dst + e)], 1);
    }
}

// ---------------------------------------------------------------------------
// K2a: per-chunk exclusive scan of g_cnt -> g_off; chunk totals -> g_bsum
// ---------------------------------------------------------------------------
__global__ void k_scan1(int n)
{
    __shared__ int sm[1024];
    int t = threadIdx.x;
    int i = blockIdx.x * 1024 + t;
    int v = (i < n) ? g_cnt[i] : 0;
    sm[t] = v;
    __syncthreads();
    #pragma unroll
    for (int off = 1; off < 1024; off <<= 1) {
        int x = (t >= off) ? sm[t - off] : 0;
        __syncthreads();
        sm[t] += x;
        __syncthreads();
    }
    if (i < n) g_off[i] = sm[t] - v;
    if (t == 1023) g_bsum[blockIdx.x] = sm[t];
}

// ---------------------------------------------------------------------------
// K2b: add chunk-prefix computed inline from <=128 chunk sums
// ---------------------------------------------------------------------------
__global__ void k_scan3(int n, int nchunks)
{
    __shared__ int sb[128];
    int t = threadIdx.x;
    if (t < nchunks) sb[t] = g_bsum[t];
    __syncthreads();
    int i = blockIdx.x * 256 + t;
    if (i >= n) return;
    int chunk = i >> 10;
    int pre = 0;
    for (int j = 0; j < chunk; j++) pre += sb[j];
    g_off[i] += pre;
}

// ---------------------------------------------------------------------------
// K3: counting-sort edges by dst. Bumps g_off (becomes segment END).
// ---------------------------------------------------------------------------
__global__ void k_perm(const int* __restrict__ src, const int* __restrict__ dst,
                       const int* __restrict__ ety, int ne)
{
    int e = blockIdx.x * 256 + threadIdx.x;
    if (e >= ne) return;
    int d = __ldg(dst + e);
    int pos = atomicAdd(&g_off[d], 1);
    g_edge[pos] = make_int2(__ldg(src + e), __ldg(ety + e));
}

// ---------------------------------------------------------------------------
// K4: one warp per node: z = (1/cnt) * sum_e (h[src_e] + rel[etype_e])
// ---------------------------------------------------------------------------
__global__ void k_agg(const float* __restrict__ rel, int n)
{
    int lane = threadIdx.x & 31;
    int node = (blockIdx.x * blockDim.x + threadIdx.x) >> 5;
    if (node >= n) return;
    int cnt = __ldg(&g_cnt[node]);
    int beg = __ldg(&g_off[node]) - cnt;

    const float4* h4 = reinterpret_cast<const float4*>(g_h);
    const float4* r4 = reinterpret_cast<const float4*>(rel);

    float4 acc = make_float4(0.f, 0.f, 0.f, 0.f);
    int j = 0;
    for (; j + 3 < cnt; j += 4) {
        int2 e0 = __ldg(&g_edge[beg + j]);
        int2 e1 = __ldg(&g_edge[beg + j + 1]);
        int2 e2 = __ldg(&g_edge[beg + j + 2]);
        int2 e3 = __ldg(&g_edge[beg + j + 3]);
        float4 a0 = __ldcg(h4 + e0.x * D4 + lane);
        float4 a1 = __ldcg(h4 + e1.x * D4 + lane);
        float4 a2 = __ldcg(h4 + e2.x * D4 + lane);
        float4 a3 = __ldcg(h4 + e3.x * D4 + lane);
        float4 b0 = __ldg(r4 + e0.y * D4 + lane);
        float4 b1 = __ldg(r4 + e1.y * D4 + lane);
        float4 b2 = __ldg(r4 + e2.y * D4 + lane);
        float4 b3 = __ldg(r4 + e3.y * D4 + lane);
        acc.x += ((a0.x + b0.x) + (a1.x + b1.x)) + ((a2.x + b2.x) + (a3.x + b3.x));
        acc.y += ((a0.y + b0.y) + (a1.y + b1.y)) + ((a2.y + b2.y) + (a3.y + b3.y));
        acc.z += ((a0.z + b0.z) + (a1.z + b1.z)) + ((a2.z + b2.z) + (a3.z + b3.z));
        acc.w += ((a0.w + b0.w) + (a1.w + b1.w)) + ((a2.w + b2.w) + (a3.w + b3.w));
    }
    for (; j < cnt; j++) {
        int2 e0 = __ldg(&g_edge[beg + j]);
        float4 a0 = __ldcg(h4 + e0.x * D4 + lane);
        float4 b0 = __ldg(r4 + e0.y * D4 + lane);
        acc.x += a0.x + b0.x;
        acc.y += a0.y + b0.y;
        acc.z += a0.z + b0.z;
        acc.w += a0.w + b0.w;
    }
    float inv = (cnt > 0) ? 1.0f / (float)cnt : 0.f;
    acc.x *= inv; acc.y *= inv; acc.z *= inv; acc.w *= inv;
    reinterpret_cast<float4*>(g_z)[node * D4 + lane] = acc;
}

// ===========================================================================
// K5: out = relu( z @ Wn + h @ Wl ) via mma.sync bf16-split (hh + hl + lh).
// deg==0 rows fall back to relu(h @ We) (their z term is exactly 0).
// Weights staged once per block as B[n][k] (k = 0..255 over [Wn;Wl]),
// hi/lo bf16, XOR swizzle (16B chunk index ^ (row & 7)) for ldmatrix.
// ===========================================================================

#define OFF_BHI 0
#define OFF_BLO 65536
#define OFF_AHI 131072
#define OFF_ALO 163840
#define OFF_DEG 196608
#define SMEM_K5 (196608 + 512)

__device__ __forceinline__ uint32_t smem_u32(const void* p) {
    uint32_t a;
    asm("{ .reg .u64 t; cvta.to.shared.u64 t, %1; cvt.u32.u64 %0, t; }"
        : "=r"(a) : "l"(p));
    return a;
}
__device__ __forceinline__ void split2(float x0, float x1,
                                       uint32_t& hi, uint32_t& lo) {
    __nv_bfloat16 h0 = __float2bfloat16(x0);
    __nv_bfloat16 h1 = __float2bfloat16(x1);
    __nv_bfloat16 l0 = __float2bfloat16(x0 - __bfloat162float(h0));
    __nv_bfloat16 l1 = __float2bfloat16(x1 - __bfloat162float(h1));
    hi = (uint32_t)__bfloat16_as_ushort(h0) |
         ((uint32_t)__bfloat16_as_ushort(h1) << 16);
    lo = (uint32_t)__bfloat16_as_ushort(l0) |
         ((uint32_t)__bfloat16_as_ushort(l1) << 16);
}
__device__ __forceinline__ void ldsm4(uint32_t* r, uint32_t addr) {
    asm volatile("ldmatrix.sync.aligned.m8n8.x4.shared.b16 {%0,%1,%2,%3}, [%4];"
                 : "=r"(r[0]), "=r"(r[1]), "=r"(r[2]), "=r"(r[3]) : "r"(addr));
}
__device__ __forceinline__ void mma16816(float* c, const uint32_t* a,
                                         const uint32_t* b) {
    asm volatile("mma.sync.aligned.m16n8k16.row.col.f32.bf16.bf16.f32 "
                 "{%0,%1,%2,%3}, {%4,%5,%6,%7}, {%8,%9}, {%0,%1,%2,%3};"
                 : "+f"(c[0]), "+f"(c[1]), "+f"(c[2]), "+f"(c[3])
                 : "r"(a[0]), "r"(a[1]), "r"(a[2]), "r"(a[3]),
                   "r"(b[0]), "r"(b[1]));
}

__global__ void __launch_bounds__(256, 1)
k_out(const float* __restrict__ Wl, const float* __restrict__ We,
      const float* __restrict__ Wn, float* __restrict__ out, int n)
{
    extern __shared__ __align__(16) char smem[];
    int* degs = reinterpret_cast<int*>(smem + OFF_DEG);
    uint32_t sBhi = smem_u32(smem + OFF_BHI);
    uint32_t sBlo = smem_u32(smem + OFF_BLO);
    uint32_t sAhi = smem_u32(smem + OFF_AHI);
    uint32_t sAlo = smem_u32(smem + OFF_ALO);

    int tid = threadIdx.x, lane = tid & 31, wid = tid >> 5;
    int rr = lane & 7, q = lane >> 3;

    // ---- stage B = [Wn; Wl] transposed to [n][k], hi/lo, swizzled (once) ----
    for (int i = tid; i < 128 * 32; i += 256) {
        int nn = i >> 5, c = i & 31;
        float v[8];
        #pragma unroll
        for (int j = 0; j < 8; j++) {
            int k = c * 8 + j;
            v[j] = (k < 128) ? __ldg(Wn + k * 128 + nn)
                             : __ldg(Wl + (k - 128) * 128 + nn);
        }
        uint32_t hi[4], lo[4];
        split2(v[0], v[1], hi[0], lo[0]);
        split2(v[2], v[3], hi[1], lo[1]);
        split2(v[4], v[5], hi[2], lo[2]);
        split2(v[6], v[7], hi[3], lo[3]);
        int cs = c ^ (nn & 7);
        *reinterpret_cast<uint4*>(smem + OFF_BHI + nn * 512 + cs * 16) =
            make_uint4(hi[0], hi[1], hi[2], hi[3]);
        *reinterpret_cast<uint4*>(smem + OFF_BLO + nn * 512 + cs * 16) =
            make_uint4(lo[0], lo[1], lo[2], lo[3]);
    }

    int ntile = (n + 127) / 128;

    for (int tile = blockIdx.x; tile < ntile; tile += gridDim.x) {
        int row0 = tile * 128;
        __syncthreads();            // previous tile epilogue done; B visible

        if (tid < 128) {
            int gr = row0 + tid;
            int c = 1;
            if (gr < n) { c = g_cnt[gr]; g_cnt[gr] = 0; }
            degs[tid] = c;
        }

        float acc[16][4];
        #pragma unroll
        for (int t2 = 0; t2 < 16; t2++)
            #pragma unroll
            for (int j = 0; j < 4; j++) acc[t2][j] = 0.f;

        #pragma unroll 1
        for (int p = 0; p < 2; p++) {
            const float* src = p ? g_h : g_z;
            if (p) __syncthreads();     // previous phase mma reads done

            // stage A (activations) hi/lo, swizzled
            #pragma unroll 1
            for (int i = tid; i < 128 * 16; i += 256) {
                int m = i >> 4, c = i & 15;
                int gr = row0 + m;
                float4 v0 = make_float4(0.f, 0.f, 0.f, 0.f), v1 = v0;
                if (gr < n) {
                    const float4* sp = reinterpret_cast<const float4*>(
                        src + (size_t)gr * 128 + c * 8);
                    v0 = __ldcg(sp);
                    v1 = __ldcg(sp + 1);
                }
                uint32_t hi[4], lo[4];
                split2(v0.x, v0.y, hi[0], lo[0]);
                split2(v0.z, v0.w, hi[1], lo[1]);
                split2(v1.x, v1.y, hi[2], lo[2]);
                split2(v1.z, v1.w, hi[3], lo[3]);
                int cs = c ^ (m & 7);
                *reinterpret_cast<uint4*>(smem + OFF_AHI + m * 256 + cs * 16) =
                    make_uint4(hi[0], hi[1], hi[2], hi[3]);
                *reinterpret_cast<uint4*>(smem + OFF_ALO + m * 256 + cs * 16) =
                    make_uint4(lo[0], lo[1], lo[2], lo[3]);
            }
            __syncthreads();

            int cb = p * 16;
            #pragma unroll 1
            for (int pass = 0; pass < 3; pass++) {
                uint32_t Ab = (pass == 2) ? sAlo : sAhi;
                uint32_t Bb = (pass == 1) ? sBlo : sBhi;
                #pragma unroll 1
                for (int kc = 0; kc < 8; kc++) {
                    uint32_t a[4];
                    {
                        int m = wid * 16 + (q & 1) * 8 + rr;
                        int c = kc * 2 + (q >> 1);
                        ldsm4(a, Ab + m * 256 + (c ^ (m & 7)) * 16);
                    }
                    #pragma unroll
                    for (int np = 0; np < 8; np++) {
                        uint32_t b[4];
                        int nn = np * 16 + (q >> 1) * 8 + rr;
                        int c = cb + kc * 2 + (q & 1);
                        ldsm4(b, Bb + nn * 512 + (c ^ (nn & 7)) * 16);
                        mma16816(acc[2 * np], a, b);
                        mma16816(acc[2 * np + 1], a, b + 2);
                    }
                }
            }
        }

        // ---- epilogue ----
        #pragma unroll
        for (int half = 0; half < 2; half++) {
            int rl = wid * 16 + (lane >> 2) + half * 8;
            int gr = row0 + rl;
            if (gr >= n) continue;
            if (degs[rl] != 0) {
                #pragma unroll
                for (int nt = 0; nt < 16; nt++) {
                    float a0 = acc[nt][2 * half], a1 = acc[nt][2 * half + 1];
                    float2 o = make_float2(a0 > 0.f ? a0 : 0.f,
                                           a1 > 0.f ? a1 : 0.f);
                    *reinterpret_cast<float2*>(
                        out + (size_t)gr * 128 + nt * 8 + (lane & 3) * 2) = o;
                }
            } else {
                // rare: no in-edges -> out = relu(h @ We); z term is 0
                int cbase = (lane & 3) * 2;
                #pragma unroll 1
                for (int nt = 0; nt < 16; nt++) {
                    float f0 = 0.f, f1 = 0.f;
                    int col = nt * 8 + cbase;
                    #pragma unroll 1
                    for (int k = 0; k < 128; k++) {
                        float hk = g_h[(size_t)gr * 128 + k];
                        f0 += hk * __ldg(We + k * 128 + col);
                        f1 += hk * __ldg(We + k * 128 + col + 1);
                    }
                    float2 o = make_float2(f0 > 0.f ? f0 : 0.f,
                                           f1 > 0.f ? f1 : 0.f);
                    *reinterpret_cast<float2*>(
                        out + (size_t)gr * 128 + col) = o;
                }
            }
        }
    }
}

// ---------------------------------------------------------------------------
extern "C" void kernel_launch(void* const* d_in, const int* in_sizes, int n_in,
                              void* d_out, int out_size)
{
    const float* prev    = (const float*)d_in[0];
    const float* rel     = (const float*)d_in[1];
    const float* Wl      = (const float*)d_in[2];
    const float* We      = (const float*)d_in[3];
    const float* Wn      = (const float*)d_in[4];
    const int*   node_id = (const int*)d_in[5];
    const int*   src     = (const int*)d_in[6];
    const int*   dst     = (const int*)d_in[7];
    const int*   ety     = (const int*)d_in[8];
    float* out = (float*)d_out;

    int n_nodes = in_sizes[5];
    int n_edges = in_sizes[6];
    int nchunks = (n_nodes + 1023) / 1024;

    int gb = (n_nodes * D4 + 255) / 256;
    int hb = (n_edges + 255) / 256;
    k_prep<<<gb + hb, 256>>>(prev, node_id, dst, n_nodes, n_edges, gb);

    k_scan1<<<nchunks, 1024>>>(n_nodes);
    k_scan3<<<(n_nodes + 255) / 256, 256>>>(n_nodes, nchunks);

    k_perm<<<(n_edges + 255) / 256, 256>>>(src, dst, ety, n_edges);

    k_agg<<<(n_nodes * 32 + 255) / 256, 256>>>(rel, n_nodes);

    cudaFuncSetAttribute(k_out, cudaFuncAttributeMaxDynamicSharedMemorySize,
                         SMEM_K5);
    k_out<<<148, 256, SMEM_K5>>>(Wl, We, Wn, out, n_nodes);
}

// round 8
// speedup vs baseline: 2.3995x; 1.0434x over previous
#include <cuda_runtime.h>
#include <cuda_bf16.h>
#include <cstdint>

#define D 128
#define D4 32
#define MAXN 50176
#define MAXE 800000

typedef unsigned long long ull;

// ---- scratch (module-static device memory, zero-initialized at load) ----
__device__ __align__(16) float g_h[MAXN * D];   // gathered node features
__device__ __align__(16) float g_z[MAXN * D];   // normalized aggregate
__device__ int   g_cnt[MAXN];                   // in-degree (zeroed by k_out)
__device__ int   g_off[MAXN];                   // chunk-local CSR offsets
__device__ int   g_bsum[128];                   // scan chunk sums
__device__ __align__(8) int2 g_edge[MAXE];      // (src, etype) sorted by dst

// ---------------------------------------------------------------------------
// K1: grid-split: gather h = prev[node_id]  |  histogram dst into g_cnt
// ---------------------------------------------------------------------------
__global__ void k_prep(const float* __restrict__ prev,
                       const int* __restrict__ node_id,
                       const int* __restrict__ dst,
                       int n, int ne, int gb)
{
    if (blockIdx.x < gb) {
        int i = blockIdx.x * 256 + threadIdx.x;
        if (i >= n * D4) return;
        int row = i >> 5, col = i & 31;
        int ent = __ldg(node_id + row);
        float4 v = __ldg(reinterpret_cast<const float4*>(prev) + (size_t)ent * D4 + col);
        reinterpret_cast<float4*>(g_h)[i] = v;
    } else {
        int e = (blockIdx.x - gb) * 256 + threadIdx.x;
        if (e >= ne) return;
        atomicAdd(&g_cnt[__ldg(dst + e)], 1);
    }
}

// ---------------------------------------------------------------------------
// K2: per-chunk exclusive scan of g_cnt -> g_off (chunk-local); totals->g_bsum
// ---------------------------------------------------------------------------
__global__ void k_scan1(int n)
{
    __shared__ int sm[1024];
    int t = threadIdx.x;
    int i = blockIdx.x * 1024 + t;
    int v = (i < n) ? g_cnt[i] : 0;
    sm[t] = v;
    __syncthreads();
    #pragma unroll
    for (int off = 1; off < 1024; off <<= 1) {
        int x = (t >= off) ? sm[t - off] : 0;
        __syncthreads();
        sm[t] += x;
        __syncthreads();
    }
    if (i < n) g_off[i] = sm[t] - v;
    if (t == 1023) g_bsum[blockIdx.x] = sm[t];
}

// ---------------------------------------------------------------------------
// K3: counting-sort edges by dst. Chunk prefix computed inline from g_bsum.
// g_off stays chunk-local (bumped to chunk-local END).
// ---------------------------------------------------------------------------
__global__ void k_perm(const int* __restrict__ src, const int* __restrict__ dst,
                       const int* __restrict__ ety, int ne, int nchunks)
{
    __shared__ int pre[128];
    int t = threadIdx.x;
    if (t == 0) {
        int run = 0;
        for (int j = 0; j < nchunks; j++) { pre[j] = run; run += g_bsum[j]; }
    }
    __syncthreads();
    int e = blockIdx.x * 256 + t;
    if (e >= ne) return;
    int d = __ldg(dst + e);
    int pos = pre[d >> 10] + atomicAdd(&g_off[d], 1);
    g_edge[pos] = make_int2(__ldg(src + e), __ldg(ety + e));
}

// ---------------------------------------------------------------------------
// K4: one warp per node: z = (1/cnt) * sum_e (h[src_e] + rel[etype_e])
// ---------------------------------------------------------------------------
__global__ void k_agg(const float* __restrict__ rel, int n, int nchunks)
{
    __shared__ int pre[128];
    if (threadIdx.x == 0) {
        int run = 0;
        for (int j = 0; j < nchunks; j++) { pre[j] = run; run += g_bsum[j]; }
    }
    __syncthreads();

    int lane = threadIdx.x & 31;
    int node = (blockIdx.x * blockDim.x + threadIdx.x) >> 5;
    if (node >= n) return;
    int cnt = __ldg(&g_cnt[node]);
    int beg = pre[node >> 10] + __ldg(&g_off[node]) - cnt;

    const float4* h4 = reinterpret_cast<const float4*>(g_h);
    const float4* r4 = reinterpret_cast<const float4*>(rel);

    float4 acc = make_float4(0.f, 0.f, 0.f, 0.f);
    int j = 0;
    for (; j + 3 < cnt; j += 4) {
        int2 e0 = __ldg(&g_edge[beg + j]);
        int2 e1 = __ldg(&g_edge[beg + j + 1]);
        int2 e2 = __ldg(&g_edge[beg + j + 2]);
        int2 e3 = __ldg(&g_edge[beg + j + 3]);
        float4 a0 = __ldcg(h4 + e0.x * D4 + lane);
        float4 a1 = __ldcg(h4 + e1.x * D4 + lane);
        float4 a2 = __ldcg(h4 + e2.x * D4 + lane);
        float4 a3 = __ldcg(h4 + e3.x * D4 + lane);
        float4 b0 = __ldg(r4 + e0.y * D4 + lane);
        float4 b1 = __ldg(r4 + e1.y * D4 + lane);
        float4 b2 = __ldg(r4 + e2.y * D4 + lane);
        float4 b3 = __ldg(r4 + e3.y * D4 + lane);
        acc.x += ((a0.x + b0.x) + (a1.x + b1.x)) + ((a2.x + b2.x) + (a3.x + b3.x));
        acc.y += ((a0.y + b0.y) + (a1.y + b1.y)) + ((a2.y + b2.y) + (a3.y + b3.y));
        acc.z += ((a0.z + b0.z) + (a1.z + b1.z)) + ((a2.z + b2.z) + (a3.z + b3.z));
        acc.w += ((a0.w + b0.w) + (a1.w + b1.w)) + ((a2.w + b2.w) + (a3.w + b3.w));
    }
    for (; j < cnt; j++) {
        int2 e0 = __ldg(&g_edge[beg + j]);
        float4 a0 = __ldcg(h4 + e0.x * D4 + lane);
        float4 b0 = __ldg(r4 + e0.y * D4 + lane);
        acc.x += a0.x + b0.x;
        acc.y += a0.y + b0.y;
        acc.z += a0.z + b0.z;
        acc.w += a0.w + b0.w;
    }
    float inv = (cnt > 0) ? 1.0f / (float)cnt : 0.f;
    acc.x *= inv; acc.y *= inv; acc.z *= inv; acc.w *= inv;
    reinterpret_cast<float4*>(g_z)[node * D4 + lane] = acc;
}

// ===========================================================================
// K5: out = relu( z @ Wn + h @ Wl ) via mma.sync bf16-split (hh + hl + lh).
// 512 threads (16 warps): warp = (wm = wid&7 -> 16 rows, wn = wid>>3 -> 64 cols).
// deg==0 rows fall back to relu(h @ We).
// ===========================================================================

#define OFF_BHI 0
#define OFF_BLO 65536
#define OFF_AHI 131072
#define OFF_ALO 163840
#define OFF_DEG 196608
#define SMEM_K5 (196608 + 512)

__device__ __forceinline__ uint32_t smem_u32(const void* p) {
    uint32_t a;
    asm("{ .reg .u64 t; cvta.to.shared.u64 t, %1; cvt.u32.u64 %0, t; }"
        : "=r"(a) : "l"(p));
    return a;
}
__device__ __forceinline__ void split2(float x0, float x1,
                                       uint32_t& hi, uint32_t& lo) {
    __nv_bfloat16 h0 = __float2bfloat16(x0);
    __nv_bfloat16 h1 = __float2bfloat16(x1);
    __nv_bfloat16 l0 = __float2bfloat16(x0 - __bfloat162float(h0));
    __nv_bfloat16 l1 = __float2bfloat16(x1 - __bfloat162float(h1));
    hi = (uint32_t)__bfloat16_as_ushort(h0) |
         ((uint32_t)__bfloat16_as_ushort(h1) << 16);
    lo = (uint32_t)__bfloat16_as_ushort(l0) |
         ((uint32_t)__bfloat16_as_ushort(l1) << 16);
}
__device__ __forceinline__ void ldsm4(uint32_t* r, uint32_t addr) {
    asm volatile("ldmatrix.sync.aligned.m8n8.x4.shared.b16 {%0,%1,%2,%3}, [%4];"
                 : "=r"(r[0]), "=r"(r[1]), "=r"(r[2]), "=r"(r[3]) : "r"(addr));
}
__device__ __forceinline__ void mma16816(float* c, const uint32_t* a,
                                         const uint32_t* b) {
    asm volatile("mma.sync.aligned.m16n8k16.row.col.f32.bf16.bf16.f32 "
                 "{%0,%1,%2,%3}, {%4,%5,%6,%7}, {%8,%9}, {%0,%1,%2,%3};"
                 : "+f"(c[0]), "+f"(c[1]), "+f"(c[2]), "+f"(c[3])
                 : "r"(a[0]), "r"(a[1]), "r"(a[2]), "r"(a[3]),
                   "r"(b[0]), "r"(b[1]));
}

__global__ void __launch_bounds__(512, 1)
k_out(const float* __restrict__ Wl, const float* __restrict__ We,
      const float* __restrict__ Wn, float* __restrict__ out, int n)
{
    extern __shared__ __align__(16) char smem[];
    int* degs = reinterpret_cast<int*>(smem + OFF_DEG);
    uint32_t sBhi = smem_u32(smem + OFF_BHI);
    uint32_t sBlo = smem_u32(smem + OFF_BLO);
    uint32_t sAhi = smem_u32(smem + OFF_AHI);
    uint32_t sAlo = smem_u32(smem + OFF_ALO);

    int tid = threadIdx.x, lane = tid & 31, wid = tid >> 5;
    int wm = wid & 7, wn = wid >> 3;      // row-warp, col-warp
    int rr = lane & 7, q = lane >> 3;

    // ---- stage B = [Wn; Wl] transposed to [n][k], hi/lo, swizzled (once) ----
    for (int i = tid; i < 128 * 32; i += 512) {
        int nn = i >> 5, c = i & 31;
        float v[8];
        #pragma unroll
        for (int j = 0; j < 8; j++) {
            int k = c * 8 + j;
            v[j] = (k < 128) ? __ldg(Wn + k * 128 + nn)
                             : __ldg(Wl + (k - 128) * 128 + nn);
        }
        uint32_t hi[4], lo[4];
        split2(v[0], v[1], hi[0], lo[0]);
        split2(v[2], v[3], hi[1], lo[1]);
        split2(v[4], v[5], hi[2], lo[2]);
        split2(v[6], v[7], hi[3], lo[3]);
        int cs = c ^ (nn & 7);
        *reinterpret_cast<uint4*>(smem + OFF_BHI + nn * 512 + cs * 16) =
            make_uint4(hi[0], hi[1], hi[2], hi[3]);
        *reinterpret_cast<uint4*>(smem + OFF_BLO + nn * 512 + cs * 16) =
            make_uint4(lo[0], lo[1], lo[2], lo[3]);
    }

    int ntile = (n + 127) / 128;

    for (int tile = blockIdx.x; tile < ntile; tile += gridDim.x) {
        int row0 = tile * 128;
        __syncthreads();            // previous tile epilogue done; B visible

        if (tid < 128) {
            int gr = row0 + tid;
            int c = 1;
            if (gr < n) { c = g_cnt[gr]; g_cnt[gr] = 0; }
            degs[tid] = c;
        }

        float acc[8][4];
        #pragma unroll
        for (int t2 = 0; t2 < 8; t2++)
            #pragma unroll
            for (int j = 0; j < 4; j++) acc[t2][j] = 0.f;

        #pragma unroll 1
        for (int p = 0; p < 2; p++) {
            const float* src = p ? g_h : g_z;
            if (p) __syncthreads();     // previous phase mma reads done

            // stage A (activations) hi/lo, swizzled
            #pragma unroll 1
            for (int i = tid; i < 128 * 16; i += 512) {
                int m = i >> 4, c = i & 15;
                int gr = row0 + m;
                float4 v0 = make_float4(0.f, 0.f, 0.f, 0.f), v1 = v0;
                if (gr < n) {
                    const float4* sp = reinterpret_cast<const float4*>(
                        src + (size_t)gr * 128 + c * 8);
                    v0 = __ldcg(sp);
                    v1 = __ldcg(sp + 1);
                }
                uint32_t hi[4], lo[4];
                split2(v0.x, v0.y, hi[0], lo[0]);
                split2(v0.z, v0.w, hi[1], lo[1]);
                split2(v1.x, v1.y, hi[2], lo[2]);
                split2(v1.z, v1.w, hi[3], lo[3]);
                int cs = c ^ (m & 7);
                *reinterpret_cast<uint4*>(smem + OFF_AHI + m * 256 + cs * 16) =
                    make_uint4(hi[0], hi[1], hi[2], hi[3]);
                *reinterpret_cast<uint4*>(smem + OFF_ALO + m * 256 + cs * 16) =
                    make_uint4(lo[0], lo[1], lo[2], lo[3]);
            }
            __syncthreads();

            int cb = p * 16;
            #pragma unroll 1
            for (int pass = 0; pass < 3; pass++) {
                uint32_t Ab = (pass == 2) ? sAlo : sAhi;
                uint32_t Bb = (pass == 1) ? sBlo : sBhi;
                #pragma unroll 1
                for (int kc = 0; kc < 8; kc++) {
                    uint32_t a[4];
                    {
                        int m = wm * 16 + (q & 1) * 8 + rr;
                        int c = kc * 2 + (q >> 1);
                        ldsm4(a, Ab + m * 256 + (c ^ (m & 7)) * 16);
                    }
                    #pragma unroll
                    for (int np = 0; np < 4; np++) {
                        uint32_t b[4];
                        int nn = wn * 64 + np * 16 + (q >> 1) * 8 + rr;
                        int c = cb + kc * 2 + (q & 1);
                        ldsm4(b, Bb + nn * 512 + (c ^ (nn & 7)) * 16);
                        mma16816(acc[2 * np], a, b);
                        mma16816(acc[2 * np + 1], a, b + 2);
                    }
                }
            }
        }

        // ---- epilogue: warp covers rows wm*16..+16, cols wn*64..+64 ----
        #pragma unroll
        for (int half = 0; half < 2; half++) {
            int rl = wm * 16 + (lane >> 2) + half * 8;
            int gr = row0 + rl;
            if (gr >= n) continue;
            if (degs[rl] != 0) {
                #pragma unroll
                for (int nt = 0; nt < 8; nt++) {
                    float a0 = acc[nt][2 * half], a1 = acc[nt][2 * half + 1];
                    float2 o = make_float2(a0 > 0.f ? a0 : 0.f,
                                           a1 > 0.f ? a1 : 0.f);
                    *reinterpret_cast<float2*>(
                        out + (size_t)gr * 128 + wn * 64 + nt * 8 + (lane & 3) * 2) = o;
                }
            } else {
                // rare: no in-edges -> out = relu(h @ We); z term is 0
                int cbase = (lane & 3) * 2;
                #pragma unroll 1
                for (int nt = 0; nt < 8; nt++) {
                    float f0 = 0.f, f1 = 0.f;
                    int col = wn * 64 + nt * 8 + cbase;
                    #pragma unroll 1
                    for (int k = 0; k < 128; k++) {
                        float hk = g_h[(size_t)gr * 128 + k];
                        f0 += hk * __ldg(We + k * 128 + col);
                        f1 += hk * __ldg(We + k * 128 + col + 1);
                    }
                    float2 o = make_float2(f0 > 0.f ? f0 : 0.f,
                                           f1 > 0.f ? f1 : 0.f);
                    *reinterpret_cast<float2*>(
                        out + (size_t)gr * 128 + col) = o;
                }
            }
        }
    }
}

// ---------------------------------------------------------------------------
extern "C" void kernel_launch(void* const* d_in, const int* in_sizes, int n_in,
                              void* d_out, int out_size)
{
    const float* prev    = (const float*)d_in[0];
    const float* rel     = (const float*)d_in[1];
    const float* Wl      = (const float*)d_in[2];
    const float* We      = (const float*)d_in[3];
    const float* Wn      = (const float*)d_in[4];
    const int*   node_id = (const int*)d_in[5];
    const int*   src     = (const int*)d_in[6];
    const int*   dst     = (const int*)d_in[7];
    const int*   ety     = (const int*)d_in[8];
    float* out = (float*)d_out;

    int n_nodes = in_sizes[5];
    int n_edges = in_sizes[6];
    int nchunks = (n_nodes + 1023) / 1024;

    int gb = (n_nodes * D4 + 255) / 256;
    int hb = (n_edges + 255) / 256;
    k_prep<<<gb + hb, 256>>>(prev, node_id, dst, n_nodes, n_edges, gb);

    k_scan1<<<nchunks, 1024>>>(n_nodes);

    k_perm<<<(n_edges + 255) / 256, 256>>>(src, dst, ety, n_edges, nchunks);

    k_agg<<<(n_nodes * 32 + 255) / 256, 256>>>(rel, n_nodes, nchunks);

    cudaFuncSetAttribute(k_out, cudaFuncAttributeMaxDynamicSharedMemorySize,
                         SMEM_K5);
    k_out<<<148, 512, SMEM_K5>>>(Wl, We, Wn, out, n_nodes);
}

// round 9
// speedup vs baseline: 2.4352x; 1.0148x over previous
#include <cuda_runtime.h>
#include <cuda_bf16.h>
#include <cstdint>

#define D 128
#define D4 32
#define MAXN 50176
#define MAXE 800000

typedef unsigned long long ull;

// ---- scratch (module-static device memory, zero-initialized at load) ----
__device__ __align__(16) float g_h[MAXN * D];           // fp32 h (agg + fallback)
__device__ __align__(16) unsigned short g_ha[MAXN * D]; // h hi bf16, pre-swizzled rows
__device__ __align__(16) unsigned short g_la[MAXN * D]; // h lo bf16
__device__ __align__(16) unsigned short g_za[MAXN * D]; // z hi bf16
__device__ __align__(16) unsigned short g_zl[MAXN * D]; // z lo bf16
__device__ int   g_cnt[MAXN];
__device__ int   g_off[MAXN];                           // chunk-local CSR offsets
__device__ int   g_bsum[128];
__device__ __align__(8) int2 g_edge[MAXE];

__device__ __forceinline__ void split2(float x0, float x1,
                                       uint32_t& hi, uint32_t& lo) {
    __nv_bfloat16 h0 = __float2bfloat16(x0);
    __nv_bfloat16 h1 = __float2bfloat16(x1);
    __nv_bfloat16 l0 = __float2bfloat16(x0 - __bfloat162float(h0));
    __nv_bfloat16 l1 = __float2bfloat16(x1 - __bfloat162float(h1));
    hi = (uint32_t)__bfloat16_as_ushort(h0) |
         ((uint32_t)__bfloat16_as_ushort(h1) << 16);
    lo = (uint32_t)__bfloat16_as_ushort(l0) |
         ((uint32_t)__bfloat16_as_ushort(l1) << 16);
}

// ---------------------------------------------------------------------------
// K1: grid-split: gather h (fp32 + pre-swizzled bf16 hi/lo)  |  histogram dst
// ---------------------------------------------------------------------------
__global__ void k_prep(const float* __restrict__ prev,
                       const int* __restrict__ node_id,
                       const int* __restrict__ dst,
                       int n, int ne, int gb)
{
    if (blockIdx.x < gb) {
        int i = blockIdx.x * 256 + threadIdx.x;
        if (i >= n * D4) return;
        int row = i >> 5, col = i & 31;
        int ent = __ldg(node_id + row);
        float4 v = __ldg(reinterpret_cast<const float4*>(prev) + (size_t)ent * D4 + col);
        reinterpret_cast<float4*>(g_h)[i] = v;
        uint32_t h01, l01, h23, l23;
        split2(v.x, v.y, h01, l01);
        split2(v.z, v.w, h23, l23);
        int off = ((col >> 1) ^ (row & 7)) * 16 + (col & 1) * 8;
        *reinterpret_cast<uint2*>((char*)g_ha + (size_t)row * 256 + off) = make_uint2(h01, h23);
        *reinterpret_cast<uint2*>((char*)g_la + (size_t)row * 256 + off) = make_uint2(l01, l23);
    } else {
        int e = (blockIdx.x - gb) * 256 + threadIdx.x;
        if (e >= ne) return;
        atomicAdd(&g_cnt[__ldg(dst + e)], 1);
    }
}

// ---------------------------------------------------------------------------
// K2: per-chunk exclusive scan of g_cnt -> g_off (chunk-local); totals->g_bsum
// ---------------------------------------------------------------------------
__global__ void k_scan1(int n)
{
    __shared__ int sm[1024];
    int t = threadIdx.x;
    int i = blockIdx.x * 1024 + t;
    int v = (i < n) ? g_cnt[i] : 0;
    sm[t] = v;
    __syncthreads();
    #pragma unroll
    for (int off = 1; off < 1024; off <<= 1) {
        int x = (t >= off) ? sm[t - off] : 0;
        __syncthreads();
        sm[t] += x;
        __syncthreads();
    }
    if (i < n) g_off[i] = sm[t] - v;
    if (t == 1023) g_bsum[blockIdx.x] = sm[t];
}

// ---------------------------------------------------------------------------
// K3: counting-sort edges by dst; chunk prefix computed inline from g_bsum
// ---------------------------------------------------------------------------
__global__ void k_perm(const int* __restrict__ src, const int* __restrict__ dst,
                       const int* __restrict__ ety, int ne, int nchunks)
{
    __shared__ int pre[128];
    int t = threadIdx.x;
    if (t == 0) {
        int run = 0;
        for (int j = 0; j < nchunks; j++) { pre[j] = run; run += g_bsum[j]; }
    }
    __syncthreads();
    int e = blockIdx.x * 256 + t;
    if (e >= ne) return;
    int d = __ldg(dst + e);
    int pos = pre[d >> 10] + atomicAdd(&g_off[d], 1);
    g_edge[pos] = make_int2(__ldg(src + e), __ldg(ety + e));
}

// ---------------------------------------------------------------------------
// K4: one warp per node: z = (1/cnt) * sum_e (h[src_e] + rel[etype_e]);
// writes z as pre-swizzled bf16 hi/lo.
// ---------------------------------------------------------------------------
__global__ void k_agg(const float* __restrict__ rel, int n, int nchunks)
{
    __shared__ int pre[128];
    if (threadIdx.x == 0) {
        int run = 0;
        for (int j = 0; j < nchunks; j++) { pre[j] = run; run += g_bsum[j]; }
    }
    __syncthreads();

    int lane = threadIdx.x & 31;
    int node = (blockIdx.x * blockDim.x + threadIdx.x) >> 5;
    if (node >= n) return;
    int cnt = __ldg(&g_cnt[node]);
    int beg = pre[node >> 10] + __ldg(&g_off[node]) - cnt;

    const float4* h4 = reinterpret_cast<const float4*>(g_h);
    const float4* r4 = reinterpret_cast<const float4*>(rel);

    float4 acc = make_float4(0.f, 0.f, 0.f, 0.f);
    int j = 0;
    for (; j + 3 < cnt; j += 4) {
        int2 e0 = __ldg(&g_edge[beg + j]);
        int2 e1 = __ldg(&g_edge[beg + j + 1]);
        int2 e2 = __ldg(&g_edge[beg + j + 2]);
        int2 e3 = __ldg(&g_edge[beg + j + 3]);
        float4 a0 = __ldcg(h4 + e0.x * D4 + lane);
        float4 a1 = __ldcg(h4 + e1.x * D4 + lane);
        float4 a2 = __ldcg(h4 + e2.x * D4 + lane);
        float4 a3 = __ldcg(h4 + e3.x * D4 + lane);
        float4 b0 = __ldg(r4 + e0.y * D4 + lane);
        float4 b1 = __ldg(r4 + e1.y * D4 + lane);
        float4 b2 = __ldg(r4 + e2.y * D4 + lane);
        float4 b3 = __ldg(r4 + e3.y * D4 + lane);
        acc.x += ((a0.x + b0.x) + (a1.x + b1.x)) + ((a2.x + b2.x) + (a3.x + b3.x));
        acc.y += ((a0.y + b0.y) + (a1.y + b1.y)) + ((a2.y + b2.y) + (a3.y + b3.y));
        acc.z += ((a0.z + b0.z) + (a1.z + b1.z)) + ((a2.z + b2.z) + (a3.z + b3.z));
        acc.w += ((a0.w + b0.w) + (a1.w + b1.w)) + ((a2.w + b2.w) + (a3.w + b3.w));
    }
    for (; j < cnt; j++) {
        int2 e0 = __ldg(&g_edge[beg + j]);
        float4 a0 = __ldcg(h4 + e0.x * D4 + lane);
        float4 b0 = __ldg(r4 + e0.y * D4 + lane);
        acc.x += a0.x + b0.x;
        acc.y += a0.y + b0.y;
        acc.z += a0.z + b0.z;
        acc.w += a0.w + b0.w;
    }
    float inv = (cnt > 0) ? 1.0f / (float)cnt : 0.f;
    acc.x *= inv; acc.y *= inv; acc.z *= inv; acc.w *= inv;

    uint32_t h01, l01, h23, l23;
    split2(acc.x, acc.y, h01, l01);
    split2(acc.z, acc.w, h23, l23);
    int off = ((lane >> 1) ^ (node & 7)) * 16 + (lane & 1) * 8;
    *reinterpret_cast<uint2*>((char*)g_za + (size_t)node * 256 + off) = make_uint2(h01, h23);
    *reinterpret_cast<uint2*>((char*)g_zl + (size_t)node * 256 + off) = make_uint2(l01, l23);
}

// ===========================================================================
// K5: out = relu( z @ Wn + h @ Wl ) via mma.sync bf16-split (hh + hl + lh).
// 512 threads, 4x4 warp grid (32 rows x 32 cols per warp). A staged by
// cp.async from pre-swizzled gmem hi/lo. deg==0 rows -> relu(h @ We).
// ===========================================================================

#define OFF_BHI 0
#define OFF_BLO 65536
#define OFF_AHI 131072
#define OFF_ALO 163840
#define OFF_DEG 196608
#define SMEM_K5 (196608 + 512)

__device__ __forceinline__ uint32_t smem_u32(const void* p) {
    uint32_t a;
    asm("{ .reg .u64 t; cvta.to.shared.u64 t, %1; cvt.u32.u64 %0, t; }"
        : "=r"(a) : "l"(p));
    return a;
}
__device__ __forceinline__ void cpa16(uint32_t dst, const void* src) {
    asm volatile("cp.async.cg.shared.global [%0], [%1], 16;"
                 :: "r"(dst), "l"(src) : "memory");
}
__device__ __forceinline__ void ldsm4(uint32_t* r, uint32_t addr) {
    asm volatile("ldmatrix.sync.aligned.m8n8.x4.shared.b16 {%0,%1,%2,%3}, [%4];"
                 : "=r"(r[0]), "=r"(r[1]), "=r"(r[2]), "=r"(r[3]) : "r"(addr));
}
__device__ __forceinline__ void mma16816(float* c, const uint32_t* a,
                                         const uint32_t* b) {
    asm volatile("mma.sync.aligned.m16n8k16.row.col.f32.bf16.bf16.f32 "
                 "{%0,%1,%2,%3}, {%4,%5,%6,%7}, {%8,%9}, {%0,%1,%2,%3};"
                 : "+f"(c[0]), "+f"(c[1]), "+f"(c[2]), "+f"(c[3])
                 : "r"(a[0]), "r"(a[1]), "r"(a[2]), "r"(a[3]),
                   "r"(b[0]), "r"(b[1]));
}

__global__ void __launch_bounds__(512, 1)
k_out(const float* __restrict__ Wl, const float* __restrict__ We,
      const float* __restrict__ Wn, float* __restrict__ out, int n)
{
    extern __shared__ __align__(16) char smem[];
    int* degs = reinterpret_cast<int*>(smem + OFF_DEG);
    uint32_t sBhi = smem_u32(smem + OFF_BHI);
    uint32_t sBlo = smem_u32(smem + OFF_BLO);
    uint32_t sAhi = smem_u32(smem + OFF_AHI);
    uint32_t sAlo = smem_u32(smem + OFF_ALO);

    int tid = threadIdx.x, lane = tid & 31, wid = tid >> 5;
    int wm = wid & 3, wn = wid >> 2;      // 4x4 warp grid: 32 rows x 32 cols
    int rr = lane & 7, q = lane >> 3;

    // ---- stage B = [Wn; Wl] transposed to [n][k], hi/lo, swizzled (once) ----
    for (int i = tid; i < 128 * 32; i += 512) {
        int nn = i >> 5, c = i & 31;
        float v[8];
        #pragma unroll
        for (int j = 0; j < 8; j++) {
            int k = c * 8 + j;
            v[j] = (k < 128) ? __ldg(Wn + k * 128 + nn)
                             : __ldg(Wl + (k - 128) * 128 + nn);
        }
        uint32_t hi[4], lo[4];
        split2(v[0], v[1], hi[0], lo[0]);
        split2(v[2], v[3], hi[1], lo[1]);
        split2(v[4], v[5], hi[2], lo[2]);
        split2(v[6], v[7], hi[3], lo[3]);
        int cs = c ^ (nn & 7);
        *reinterpret_cast<uint4*>(smem + OFF_BHI + nn * 512 + cs * 16) =
            make_uint4(hi[0], hi[1], hi[2], hi[3]);
        *reinterpret_cast<uint4*>(smem + OFF_BLO + nn * 512 + cs * 16) =
            make_uint4(lo[0], lo[1], lo[2], lo[3]);
    }

    int ntile = (n + 127) / 128;

    for (int tile = blockIdx.x; tile < ntile; tile += gridDim.x) {
        int row0 = tile * 128;
        __syncthreads();            // previous tile done; B visible

        if (tid < 128) {
            int gr = row0 + tid;
            int c = 1;
            if (gr < n) { c = g_cnt[gr]; g_cnt[gr] = 0; }
            degs[tid] = c;
        }

        float acc[2][4][4];
        #pragma unroll
        for (int mt = 0; mt < 2; mt++)
            #pragma unroll
            for (int nt = 0; nt < 4; nt++)
                #pragma unroll
                for (int j2 = 0; j2 < 4; j2++) acc[mt][nt][j2] = 0.f;

        #pragma unroll 1
        for (int p = 0; p < 2; p++) {
            if (p) __syncthreads();     // previous phase mma reads done

            // stage A via cp.async: contiguous 32KB hi + 32KB lo (pre-swizzled)
            {
                const char* sh = (p ? (const char*)g_ha : (const char*)g_za)
                                 + (size_t)row0 * 256;
                const char* sl = (p ? (const char*)g_la : (const char*)g_zl)
                                 + (size_t)row0 * 256;
                #pragma unroll
                for (int j = 0; j < 4; j++) {
                    int idx = tid + j * 512;
                    cpa16(sAhi + idx * 16, sh + idx * 16);
                    cpa16(sAlo + idx * 16, sl + idx * 16);
                }
                asm volatile("cp.async.commit_group;" ::: "memory");
                asm volatile("cp.async.wait_group 0;" ::: "memory");
            }
            __syncthreads();

            int cb = p * 16;
            #pragma unroll 1
            for (int pass = 0; pass < 3; pass++) {
                uint32_t Ab = (pass == 2) ? sAlo : sAhi;
                uint32_t Bb = (pass == 1) ? sBlo : sBhi;
                #pragma unroll 1
                for (int kc = 0; kc < 8; kc++) {
                    uint32_t a0[4], a1[4];
                    int ca = kc * 2 + (q >> 1);
                    int m0 = wm * 32 + (q & 1) * 8 + rr;
                    ldsm4(a0, Ab + m0 * 256 + ((ca ^ (m0 & 7)) * 16));
                    int m1 = m0 + 16;
                    ldsm4(a1, Ab + m1 * 256 + ((ca ^ (m1 & 7)) * 16));
                    #pragma unroll
                    for (int nb = 0; nb < 2; nb++) {
                        uint32_t b[4];
                        int nn = wn * 32 + nb * 16 + (q >> 1) * 8 + rr;
                        int c = cb + kc * 2 + (q & 1);
                        ldsm4(b, Bb + nn * 512 + ((c ^ (nn & 7)) * 16));
                        mma16816(acc[0][2 * nb],     a0, b);
                        mma16816(acc[0][2 * nb + 1], a0, b + 2);
                        mma16816(acc[1][2 * nb],     a1, b);
                        mma16816(acc[1][2 * nb + 1], a1, b + 2);
                    }
                }
            }
        }

        // ---- epilogue: warp covers rows wm*32 + mt*16, cols wn*32..+32 ----
        #pragma unroll
        for (int mt = 0; mt < 2; mt++) {
            #pragma unroll
            for (int half = 0; half < 2; half++) {
                int rl = wm * 32 + mt * 16 + half * 8 + (lane >> 2);
                int gr = row0 + rl;
                if (gr >= n) continue;
                if (degs[rl] != 0) {
                    #pragma unroll
                    for (int nt = 0; nt < 4; nt++) {
                        float a0 = acc[mt][nt][2 * half];
                        float a1 = acc[mt][nt][2 * half + 1];
                        float2 o = make_float2(a0 > 0.f ? a0 : 0.f,
                                               a1 > 0.f ? a1 : 0.f);
                        *reinterpret_cast<float2*>(
                            out + (size_t)gr * 128 + wn * 32 + nt * 8 + (lane & 3) * 2) = o;
                    }
                } else {
                    // rare: no in-edges -> out = relu(h @ We); z term is 0
                    int cbase = (lane & 3) * 2;
                    #pragma unroll 1
                    for (int nt = 0; nt < 4; nt++) {
                        float f0 = 0.f, f1 = 0.f;
                        int col = wn * 32 + nt * 8 + cbase;
                        #pragma unroll 1
                        for (int k = 0; k < 128; k++) {
                            float hk = g_h[(size_t)gr * 128 + k];
                            f0 += hk * __ldg(We + k * 128 + col);
                            f1 += hk * __ldg(We + k * 128 + col + 1);
                        }
                        float2 o = make_float2(f0 > 0.f ? f0 : 0.f,
                                               f1 > 0.f ? f1 : 0.f);
                        *reinterpret_cast<float2*>(
                            out + (size_t)gr * 128 + col) = o;
                    }
                }
            }
        }
    }
}

// ---------------------------------------------------------------------------
extern "C" void kernel_launch(void* const* d_in, const int* in_sizes, int n_in,
                              void* d_out, int out_size)
{
    const float* prev    = (const float*)d_in[0];
    const float* rel     = (const float*)d_in[1];
    const float* Wl      = (const float*)d_in[2];
    const float* We      = (const float*)d_in[3];
    const float* Wn      = (const float*)d_in[4];
    const int*   node_id = (const int*)d_in[5];
    const int*   src     = (const int*)d_in[6];
    const int*   dst     = (const int*)d_in[7];
    const int*   ety     = (const int*)d_in[8];
    float* out = (float*)d_out;

    int n_nodes = in_sizes[5];
    int n_edges = in_sizes[6];
    int nchunks = (n_nodes + 1023) / 1024;

    int gb = (n_nodes * D4 + 255) / 256;
    int hb = (n_edges + 255) / 256;
    k_prep<<<gb + hb, 256>>>(prev, node_id, dst, n_nodes, n_edges, gb);

    k_scan1<<<nchunks, 1024>>>(n_nodes);

    k_perm<<<(n_edges + 255) / 256, 256>>>(src, dst, ety, n_edges, nchunks);

    k_agg<<<(n_nodes * 32 + 255) / 256, 256>>>(rel, n_nodes, nchunks);

    cudaFuncSetAttribute(k_out, cudaFuncAttributeMaxDynamicSharedMemorySize,
                         SMEM_K5);
    k_out<<<148, 512, SMEM_K5>>>(Wl, We, Wn, out, n_nodes);
}